// round 2
// baseline (speedup 1.0000x reference)
#include <cuda_runtime.h>
#include <cuda_bf16.h>
#include <math.h>

// Fixed problem shapes
#define B_   64
#define M_   80
#define TOUT 2000
#define TIN  400

#define N_MEL   (B_ * M_ * TOUT)          // 10,240,000
#define N_MEL4  (N_MEL / 4)               // 2,560,000
#define N_GATE  (B_ * TOUT)               // 128,000
#define N_GATE4 (N_GATE / 4)              // 32,000
#define N_ROWS  (B_ * TOUT)               // 128,000 alignment rows
#define TIN4    (TIN / 4)                 // 100 float4 per row

#define INV2SIG2 3.125f                   // 1/(2*0.4^2)

// Block partition (one wave at occupancy 6 on 148 SMs = 888 blocks)
#define G_MEL   330
#define G_GATE  4
#define G_ALIGN 554
#define G_TOTAL (G_MEL + G_GATE + G_ALIGN)

// Accumulators: 0=mel1, 1=mel2, 2=gate, 3=att, 4=ga  (zero-initialized statics;
// finalize_kernel re-zeroes them after reading, so every graph replay starts clean)
__device__ double g_acc[5];

__device__ __forceinline__ float warp_sum(float v) {
    #pragma unroll
    for (int o = 16; o > 0; o >>= 1)
        v += __shfl_xor_sync(0xFFFFFFFFu, v, o);
    return v;
}

// block-reduce two values, one double atomicAdd each
__device__ __forceinline__ void block_reduce2_atomic(float a, float b, int idx_a, int idx_b) {
    __shared__ float sa[8], sb[8];
    int lane = threadIdx.x & 31;
    int wid  = threadIdx.x >> 5;
    a = warp_sum(a);
    b = warp_sum(b);
    if (lane == 0) { sa[wid] = a; sb[wid] = b; }
    __syncthreads();
    if (wid == 0) {
        int nw = blockDim.x >> 5;
        a = (lane < nw) ? sa[lane] : 0.0f;
        b = (lane < nw) ? sb[lane] : 0.0f;
        a = warp_sum(a);
        b = warp_sum(b);
        if (lane == 0) {
            atomicAdd(&g_acc[idx_a], (double)a);
            atomicAdd(&g_acc[idx_b], (double)b);
        }
    }
}

__device__ __forceinline__ float bce1(float x, float z) {
    return fmaxf(x, 0.0f) - x * z + log1pf(expf(-fabsf(x)));
}

__global__ void __launch_bounds__(256, 6)
fused_kernel(const float4* __restrict__ mo,
             const float4* __restrict__ mp,
             const float4* __restrict__ mt,
             const float4* __restrict__ go,
             const float4* __restrict__ gt,
             const float4* __restrict__ al,
             const int*    __restrict__ in_len,
             const int*    __restrict__ out_len) {
    int blk = blockIdx.x;

    if (blk < G_MEL) {
        // ---------------- Mel L1 (decoder + postnet), single pass ----------------
        float s1 = 0.0f, s2 = 0.0f;
        int stride = G_MEL * 256;
        for (int i = blk * 256 + threadIdx.x; i < N_MEL4; i += stride) {
            float4 a = mo[i];
            float4 p = mp[i];
            float4 t = mt[i];
            s1 += fabsf(a.x - t.x) + fabsf(a.y - t.y) + fabsf(a.z - t.z) + fabsf(a.w - t.w);
            s2 += fabsf(p.x - t.x) + fabsf(p.y - t.y) + fabsf(p.z - t.z) + fabsf(p.w - t.w);
        }
        block_reduce2_atomic(s1, s2, 0, 1);
    } else if (blk < G_MEL + G_GATE) {
        // ---------------- Gate BCE-with-logits ----------------
        int lblk = blk - G_MEL;
        float s = 0.0f;
        int stride = G_GATE * 256;
        for (int i = lblk * 256 + threadIdx.x; i < N_GATE4; i += stride) {
            float4 x = go[i];
            float4 z = gt[i];
            s += bce1(x.x, z.x) + bce1(x.y, z.y) + bce1(x.z, z.z) + bce1(x.w, z.w);
        }
        block_reduce2_atomic(s, 0.0f, 2, 2); // second add of 0.0 is harmless
    } else {
        // ---------------- Alignments: att + guided-attention, warp-per-row ----------------
        int lblk = blk - G_MEL - G_GATE;
        int lane = threadIdx.x & 31;
        int warp = (lblk << 3) | (threadIdx.x >> 5);   // global warp id in align section
        int warp_stride = G_ALIGN * 8;

        float s_att = 0.0f, s_ga = 0.0f;
        for (int row = warp; row < N_ROWS; row += warp_stride) {
            int b  = row / TOUT;
            int i  = row - b * TOUT;
            int li = __ldg(&in_len[b]);
            int lo = __ldg(&out_len[b]);
            float scale  = __fdividef((float)lo, (float)li);  // hoisted: once per row
            float scale4 = 4.0f * scale;
            float fi     = (float)i;
            bool  irow_valid = (i < lo);
            const float4* rp = al + (long)row * TIN4;

            // d at j = 4*lane for first iteration; advances by -32*scale... recompute
            for (int j4 = lane; j4 < TIN4; j4 += 32) {
                float4 a = rp[j4];
                int j0 = j4 << 2;

                // att: strictly below diagonal (j < i)
                float ax = (j0     < i) ? a.x : 0.0f;
                float ay = (j0 + 1 < i) ? a.y : 0.0f;
                float az = (j0 + 2 < i) ? a.z : 0.0f;
                float aw = (j0 + 3 < i) ? a.w : 0.0f;
                s_att += (ax + ay) + (az + aw);

                // guided attention (warp-uniform branch on irow_valid)
                if (irow_valid) {
                    float d0 = fmaf((float)j0, -scale, fi);
                    float d1 = d0 - scale;
                    float d2 = d1 - scale;
                    float d3 = d2 - scale;
                    float w0 = 1.0f - __expf(-d0 * d0 * INV2SIG2);
                    float w1 = 1.0f - __expf(-d1 * d1 * INV2SIG2);
                    float w2 = 1.0f - __expf(-d2 * d2 * INV2SIG2);
                    float w3 = 1.0f - __expf(-d3 * d3 * INV2SIG2);
                    float g0 = (j0     < li) ? a.x * w0 : 0.0f;
                    float g1 = (j0 + 1 < li) ? a.y * w1 : 0.0f;
                    float g2 = (j0 + 2 < li) ? a.z * w2 : 0.0f;
                    float g3 = (j0 + 3 < li) ? a.w * w3 : 0.0f;
                    s_ga += (g0 + g1) + (g2 + g3);
                }
            }
        }
        block_reduce2_atomic(s_att, s_ga, 3, 4);
    }
}

// ---------------- Finalize: write outputs, then reset accumulators ----------------
__global__ void finalize_kernel(float* __restrict__ out) {
    if (threadIdx.x == 0) {
        double mel  = (g_acc[0] + g_acc[1]) / (double)N_MEL;
        double gate = g_acc[2] / (double)N_GATE;
        double att  = g_acc[3] / (double)B_;
        double ga   = g_acc[4] / (double)B_;
        double total = mel + gate + 0.1 * att + 0.1 * ga;
        out[0] = (float)total;
        out[1] = (float)mel;
        out[2] = (float)gate;
        out[3] = (float)att;
        out[4] = (float)ga;
        // reset for next replay
        g_acc[0] = 0.0; g_acc[1] = 0.0; g_acc[2] = 0.0;
        g_acc[3] = 0.0; g_acc[4] = 0.0;
    }
}

extern "C" void kernel_launch(void* const* d_in, const int* in_sizes, int n_in,
                              void* d_out, int out_size) {
    const float* mel_out         = (const float*)d_in[0];
    const float* mel_out_postnet = (const float*)d_in[1];
    const float* gate_out        = (const float*)d_in[2];
    const float* alignments      = (const float*)d_in[3];
    const float* mel_target      = (const float*)d_in[4];
    const float* gate_target     = (const float*)d_in[5];
    const int*   input_lengths   = (const int*)d_in[6];
    const int*   output_lengths  = (const int*)d_in[7];
    float* out = (float*)d_out;

    fused_kernel<<<G_TOTAL, 256>>>((const float4*)mel_out,
                                   (const float4*)mel_out_postnet,
                                   (const float4*)mel_target,
                                   (const float4*)gate_out,
                                   (const float4*)gate_target,
                                   (const float4*)alignments,
                                   input_lengths, output_lengths);

    finalize_kernel<<<1, 32>>>(out);
}

// round 3
// speedup vs baseline: 1.1270x; 1.1270x over previous
#include <cuda_runtime.h>
#include <cuda_bf16.h>
#include <math.h>

// Fixed problem shapes
#define B_   64
#define M_   80
#define TOUT 2000
#define TIN  400

#define N_MEL   (B_ * M_ * TOUT)          // 10,240,000
#define N_MEL4  (N_MEL / 4)               // 2,560,000
#define N_GATE  (B_ * TOUT)               // 128,000
#define N_GATE4 (N_GATE / 4)              // 32,000
#define N_ROWS  (B_ * TOUT)               // 128,000 alignment rows
#define N_AL4   (N_ROWS * 100)            // 12,800,000 float4
#define TIN4    (TIN / 4)                 // 100 float4 per row

#define INV2SIG2 3.125f                   // 1/(2*0.4^2)
#define BAND     2.45f                    // exp(-3.125*2.45^2) ~ 6e-9 (negligible)

// Block partition: exactly one wave at occupancy 6 on 148 SMs = 888 blocks.
#define G_MEL   336
#define G_GATE  4
#define G_CORR  16
#define G_ALIGN 532
#define G_TOTAL (G_MEL + G_GATE + G_CORR + G_ALIGN)

// Accumulators: 0=mel1, 1=mel2, 2=gate, 3=att, 4=ga
// Zero-initialized statics; the last finishing block re-zeroes after reading,
// so every graph replay starts clean (deterministic).
__device__ double g_acc[5];
__device__ unsigned int g_done;

__device__ __forceinline__ float warp_sum(float v) {
    #pragma unroll
    for (int o = 16; o > 0; o >>= 1)
        v += __shfl_xor_sync(0xFFFFFFFFu, v, o);
    return v;
}

// block-reduce two values into g_acc, then completion ticket; the very last
// block of the grid computes the final outputs and resets state.
__device__ __forceinline__ void block_finish(float a, float b, int idx_a, int idx_b,
                                             float* __restrict__ out) {
    __shared__ float sa[8], sb[8];
    int lane = threadIdx.x & 31;
    int wid  = threadIdx.x >> 5;
    a = warp_sum(a);
    b = warp_sum(b);
    if (lane == 0) { sa[wid] = a; sb[wid] = b; }
    __syncthreads();
    if (wid == 0) {
        int nw = blockDim.x >> 5;
        a = (lane < nw) ? sa[lane] : 0.0f;
        b = (lane < nw) ? sb[lane] : 0.0f;
        a = warp_sum(a);
        b = warp_sum(b);
        if (lane == 0) {
            atomicAdd(&g_acc[idx_a], (double)a);
            atomicAdd(&g_acc[idx_b], (double)b);
            __threadfence();
            unsigned int t = atomicAdd(&g_done, 1u);
            if (t == (unsigned)(G_TOTAL - 1)) {
                // all blocks' atomics are visible (fence-before-ticket pattern)
                volatile double* acc = g_acc;
                double mel  = (acc[0] + acc[1]) / (double)N_MEL;
                double gate = acc[2] / (double)N_GATE;
                double att  = acc[3] / (double)B_;
                double ga   = acc[4] / (double)B_;
                double total = mel + gate + 0.1 * att + 0.1 * ga;
                out[0] = (float)total;
                out[1] = (float)mel;
                out[2] = (float)gate;
                out[3] = (float)att;
                out[4] = (float)ga;
                // reset for next replay
                acc[0] = 0.0; acc[1] = 0.0; acc[2] = 0.0; acc[3] = 0.0; acc[4] = 0.0;
                g_done = 0u;
                __threadfence();
            }
        }
    }
}

__device__ __forceinline__ float bce1(float x, float z) {
    return fmaxf(x, 0.0f) - x * z + log1pf(expf(-fabsf(x)));
}

__global__ void __launch_bounds__(256, 6)
fused_kernel(const float4* __restrict__ mo,
             const float4* __restrict__ mp,
             const float4* __restrict__ mt,
             const float4* __restrict__ go,
             const float4* __restrict__ gt,
             const float4* __restrict__ al,
             const float*  __restrict__ al_s,
             const int*    __restrict__ in_len,
             const int*    __restrict__ out_len,
             float*        __restrict__ out) {
    int blk = blockIdx.x;

    if (blk < G_MEL) {
        // ======== Mel L1 (decoder + postnet), single fused pass ========
        float s1 = 0.0f, s2 = 0.0f;
        int stride = G_MEL * 256;
        #pragma unroll 4
        for (int i = blk * 256 + threadIdx.x; i < N_MEL4; i += stride) {
            float4 a = mo[i];
            float4 p = mp[i];
            float4 t = mt[i];
            s1 += fabsf(a.x - t.x) + fabsf(a.y - t.y) + fabsf(a.z - t.z) + fabsf(a.w - t.w);
            s2 += fabsf(p.x - t.x) + fabsf(p.y - t.y) + fabsf(p.z - t.z) + fabsf(p.w - t.w);
        }
        block_finish(s1, s2, 0, 1, out);

    } else if (blk < G_MEL + G_GATE) {
        // ======== Gate BCE-with-logits ========
        int lblk = blk - G_MEL;
        float s = 0.0f;
        int stride = G_GATE * 256;
        for (int i = lblk * 256 + threadIdx.x; i < N_GATE4; i += stride) {
            float4 x = go[i];
            float4 z = gt[i];
            s += bce1(x.x, z.x) + bce1(x.y, z.y) + bce1(x.z, z.z) + bce1(x.w, z.w);
        }
        block_finish(s, 0.0f, 2, 2, out);

    } else if (blk < G_MEL + G_GATE + G_CORR) {
        // ======== Guided-attention band correction: -sum a*exp(-d^2/(2s^2)) ========
        // Only |i - j*lo/li| <= BAND contributes; that is <= 3 j per row.
        __shared__ int s_li[B_], s_lo[B_];
        if (threadIdx.x < B_) {
            s_li[threadIdx.x] = in_len[threadIdx.x];
            s_lo[threadIdx.x] = out_len[threadIdx.x];
        }
        __syncthreads();

        int lblk = blk - G_MEL - G_GATE;
        int tid  = lblk * 256 + threadIdx.x;
        int tstride = G_CORR * 256;
        float s_corr = 0.0f;
        for (int row = tid; row < N_ROWS; row += tstride) {
            int b = row / TOUT;
            int i = row - b * TOUT;
            int li = s_li[b];
            int lo = s_lo[b];
            if (i < lo) {
                float fli = (float)li, flo = (float)lo, fi = (float)i;
                float inv_scale = __fdividef(fli, flo);   // li/lo
                float scale     = __fdividef(flo, fli);   // lo/li
                int j0c = (int)floorf((fi - BAND) * inv_scale);
                const float* rp = al_s + (long)row * TIN;
                #pragma unroll
                for (int k = 0; k < 4; k++) {
                    int j = j0c + k;
                    if (j >= 0 && j < li) {
                        float d = fmaf((float)j, -scale, fi);
                        float e = __expf(-d * d * INV2SIG2);
                        s_corr += rp[j] * e;
                    }
                }
            }
        }
        block_finish(0.0f, -s_corr, 3, 4, out);

    } else {
        // ======== Alignments main pass: att + ga masked sums ========
        __shared__ int s_li[B_], s_lo[B_];
        if (threadIdx.x < B_) {
            s_li[threadIdx.x] = in_len[threadIdx.x];
            s_lo[threadIdx.x] = out_len[threadIdx.x];
        }
        __syncthreads();

        int lblk = blk - G_MEL - G_GATE - G_CORR;
        float s_att = 0.0f, s_ga = 0.0f;
        int stride = G_ALIGN * 256;
        #pragma unroll 2
        for (int idx = lblk * 256 + threadIdx.x; idx < N_AL4; idx += stride) {
            unsigned uidx = (unsigned)idx;
            unsigned j4  = uidx % TIN4;           // reciprocal-mul, cheap
            unsigned row = uidx / TIN4;
            unsigned b   = row / TOUT;
            unsigned i   = row - b * TOUT;

            float4 a = al[idx];
            float sfull = (a.x + a.y) + (a.z + a.w);
            int j0 = (int)(j4 << 2);

            // att: sum over j < i
            int limA = min((int)i, TIN);
            if (j0 + 4 <= limA) {
                s_att += sfull;
            } else if (j0 < limA) {
                s_att += ((j0     < limA ? a.x : 0.0f) + (j0 + 1 < limA ? a.y : 0.0f))
                       + ((j0 + 2 < limA ? a.z : 0.0f) + (j0 + 3 < limA ? a.w : 0.0f));
            }

            // ga main: sum over valid region (i<lo, j<li); w==1 outside the band
            int limG = ((int)i < s_lo[b]) ? s_li[b] : 0;
            if (j0 + 4 <= limG) {
                s_ga += sfull;
            } else if (j0 < limG) {
                s_ga += ((j0     < limG ? a.x : 0.0f) + (j0 + 1 < limG ? a.y : 0.0f))
                      + ((j0 + 2 < limG ? a.z : 0.0f) + (j0 + 3 < limG ? a.w : 0.0f));
            }
        }
        block_finish(s_att, s_ga, 3, 4, out);
    }
}

extern "C" void kernel_launch(void* const* d_in, const int* in_sizes, int n_in,
                              void* d_out, int out_size) {
    const float* mel_out         = (const float*)d_in[0];
    const float* mel_out_postnet = (const float*)d_in[1];
    const float* gate_out        = (const float*)d_in[2];
    const float* alignments      = (const float*)d_in[3];
    const float* mel_target      = (const float*)d_in[4];
    const float* gate_target     = (const float*)d_in[5];
    const int*   input_lengths   = (const int*)d_in[6];
    const int*   output_lengths  = (const int*)d_in[7];
    float* out = (float*)d_out;

    fused_kernel<<<G_TOTAL, 256>>>((const float4*)mel_out,
                                   (const float4*)mel_out_postnet,
                                   (const float4*)mel_target,
                                   (const float4*)gate_out,
                                   (const float4*)gate_target,
                                   (const float4*)alignments,
                                   alignments,
                                   input_lengths, output_lengths,
                                   out);
}

// round 4
// speedup vs baseline: 1.2008x; 1.0655x over previous
#include <cuda_runtime.h>
#include <cuda_bf16.h>
#include <math.h>

// Fixed problem shapes
#define B_   64
#define M_   80
#define TOUT 2000
#define TIN  400

#define N_MEL   (B_ * M_ * TOUT)          // 10,240,000
#define N_MEL4  (N_MEL / 4)               // 2,560,000
#define N_GATE  (B_ * TOUT)               // 128,000
#define N_GATE4 (N_GATE / 4)              // 32,000
#define N_ROWS  (B_ * TOUT)               // 128,000 alignment rows
#define N_AL4   (N_ROWS * 100)            // 12,800,000 float4
#define TIN4    (TIN / 4)                 // 100 float4 per row

#define INV2SIG2 3.125f                   // 1/(2*0.4^2)
#define BAND     2.45f                    // exp(-3.125*2.45^2) ~ 6e-9 (negligible)

// Block partition: one 888-block wave (148 SMs x occ 6), sized so mel/align
// sections finish together (align has ~1.3x worse bytes-per-issue).
#define G_MEL   276
#define G_GATE  4
#define G_CORR  12
#define G_ALIGN 596
#define G_TOTAL (G_MEL + G_GATE + G_CORR + G_ALIGN)

// Accumulators: 0=mel1, 1=mel2, 2=gate, 3=att, 4=ga
// Zero-initialized statics; last finishing block re-zeroes after reading.
__device__ double g_acc[5];
__device__ unsigned int g_done;

__device__ __forceinline__ float warp_sum(float v) {
    #pragma unroll
    for (int o = 16; o > 0; o >>= 1)
        v += __shfl_xor_sync(0xFFFFFFFFu, v, o);
    return v;
}

// block-reduce two values into g_acc; very last block writes outputs + resets.
__device__ __forceinline__ void block_finish(float a, float b, int idx_a, int idx_b,
                                             float* __restrict__ out) {
    __shared__ float sa[8], sb[8];
    int lane = threadIdx.x & 31;
    int wid  = threadIdx.x >> 5;
    a = warp_sum(a);
    b = warp_sum(b);
    if (lane == 0) { sa[wid] = a; sb[wid] = b; }
    __syncthreads();
    if (wid == 0) {
        int nw = blockDim.x >> 5;
        a = (lane < nw) ? sa[lane] : 0.0f;
        b = (lane < nw) ? sb[lane] : 0.0f;
        a = warp_sum(a);
        b = warp_sum(b);
        if (lane == 0) {
            atomicAdd(&g_acc[idx_a], (double)a);
            atomicAdd(&g_acc[idx_b], (double)b);
            __threadfence();
            unsigned int t = atomicAdd(&g_done, 1u);
            if (t == (unsigned)(G_TOTAL - 1)) {
                volatile double* acc = g_acc;
                double mel  = (acc[0] + acc[1]) / (double)N_MEL;
                double gate = acc[2] / (double)N_GATE;
                double att  = acc[3] / (double)B_;
                double ga   = acc[4] / (double)B_;
                double total = mel + gate + 0.1 * att + 0.1 * ga;
                out[0] = (float)total;
                out[1] = (float)mel;
                out[2] = (float)gate;
                out[3] = (float)att;
                out[4] = (float)ga;
                acc[0] = 0.0; acc[1] = 0.0; acc[2] = 0.0; acc[3] = 0.0; acc[4] = 0.0;
                g_done = 0u;
                __threadfence();
            }
        }
    }
}

__device__ __forceinline__ float bce1(float x, float z) {
    return fmaxf(x, 0.0f) - x * z + log1pf(expf(-fabsf(x)));
}

// per-float4 align contribution (att + ga masked sums)
__device__ __forceinline__ void align_elem(float4 a, int idx,
                                           const int* __restrict__ s_li,
                                           const int* __restrict__ s_lo,
                                           float& s_att, float& s_ga) {
    unsigned uidx = (unsigned)idx;
    unsigned j4  = uidx % TIN4;
    unsigned row = uidx / TIN4;
    unsigned b   = row / TOUT;
    int      i   = (int)(row - b * TOUT);
    int      j0  = (int)(j4 << 2);

    float sfull = (a.x + a.y) + (a.z + a.w);

    // att: sum over j < i
    if (j0 + 4 <= i) {
        s_att += sfull;
    } else if (j0 < i) {
        s_att += ((j0     < i ? a.x : 0.0f) + (j0 + 1 < i ? a.y : 0.0f))
               + ((j0 + 2 < i ? a.z : 0.0f) + (j0 + 3 < i ? a.w : 0.0f));
    }

    // ga main: valid region (i<lo, j<li); w==1 outside the narrow exp band
    int limG = (i < s_lo[b]) ? s_li[b] : 0;
    if (j0 + 4 <= limG) {
        s_ga += sfull;
    } else if (j0 < limG) {
        s_ga += ((j0     < limG ? a.x : 0.0f) + (j0 + 1 < limG ? a.y : 0.0f))
              + ((j0 + 2 < limG ? a.z : 0.0f) + (j0 + 3 < limG ? a.w : 0.0f));
    }
}

__global__ void __launch_bounds__(256, 6)
fused_kernel(const float4* __restrict__ mo,
             const float4* __restrict__ mp,
             const float4* __restrict__ mt,
             const float4* __restrict__ go,
             const float4* __restrict__ gt,
             const float4* __restrict__ al,
             const float*  __restrict__ al_s,
             const int*    __restrict__ in_len,
             const int*    __restrict__ out_len,
             float*        __restrict__ out) {
    int blk = blockIdx.x;

    if (blk < G_MEL) {
        // ======== Mel L1 (decoder + postnet), 2x unrolled batched loads ========
        float s1 = 0.0f, s2 = 0.0f;
        const int stride = G_MEL * 256;
        int i = blk * 256 + threadIdx.x;
        for (; i + stride < N_MEL4; i += 2 * stride) {
            float4 a0 = mo[i], a1 = mo[i + stride];
            float4 p0 = mp[i], p1 = mp[i + stride];
            float4 t0 = mt[i], t1 = mt[i + stride];
            s1 += fabsf(a0.x - t0.x) + fabsf(a0.y - t0.y) + fabsf(a0.z - t0.z) + fabsf(a0.w - t0.w);
            s2 += fabsf(p0.x - t0.x) + fabsf(p0.y - t0.y) + fabsf(p0.z - t0.z) + fabsf(p0.w - t0.w);
            s1 += fabsf(a1.x - t1.x) + fabsf(a1.y - t1.y) + fabsf(a1.z - t1.z) + fabsf(a1.w - t1.w);
            s2 += fabsf(p1.x - t1.x) + fabsf(p1.y - t1.y) + fabsf(p1.z - t1.z) + fabsf(p1.w - t1.w);
        }
        for (; i < N_MEL4; i += stride) {
            float4 a = mo[i], p = mp[i], t = mt[i];
            s1 += fabsf(a.x - t.x) + fabsf(a.y - t.y) + fabsf(a.z - t.z) + fabsf(a.w - t.w);
            s2 += fabsf(p.x - t.x) + fabsf(p.y - t.y) + fabsf(p.z - t.z) + fabsf(p.w - t.w);
        }
        block_finish(s1, s2, 0, 1, out);

    } else if (blk < G_MEL + G_GATE) {
        // ======== Gate BCE-with-logits ========
        int lblk = blk - G_MEL;
        float s = 0.0f;
        const int stride = G_GATE * 256;
        for (int i = lblk * 256 + threadIdx.x; i < N_GATE4; i += stride) {
            float4 x = go[i];
            float4 z = gt[i];
            s += bce1(x.x, z.x) + bce1(x.y, z.y) + bce1(x.z, z.z) + bce1(x.w, z.w);
        }
        block_finish(s, 0.0f, 2, 2, out);

    } else if (blk < G_MEL + G_GATE + G_CORR) {
        // ======== Guided-attention band correction: -sum a*exp(-d^2/(2s^2)) ========
        __shared__ int s_li[B_], s_lo[B_];
        if (threadIdx.x < B_) {
            s_li[threadIdx.x] = in_len[threadIdx.x];
            s_lo[threadIdx.x] = out_len[threadIdx.x];
        }
        __syncthreads();

        int lblk = blk - G_MEL - G_GATE;
        int tid  = lblk * 256 + threadIdx.x;
        const int tstride = G_CORR * 256;
        float s_corr = 0.0f;
        for (int row = tid; row < N_ROWS; row += tstride) {
            int b = row / TOUT;
            int i = row - b * TOUT;
            int li = s_li[b];
            int lo = s_lo[b];
            if (i < lo) {
                float fli = (float)li, flo = (float)lo, fi = (float)i;
                float inv_scale = __fdividef(fli, flo);   // li/lo
                float scale     = __fdividef(flo, fli);   // lo/li
                int j0c = (int)floorf((fi - BAND) * inv_scale);
                const float* rp = al_s + (long)row * TIN;
                #pragma unroll
                for (int k = 0; k < 4; k++) {
                    int j = j0c + k;
                    if (j >= 0 && j < li) {
                        float d = fmaf((float)j, -scale, fi);
                        float e = __expf(-d * d * INV2SIG2);
                        s_corr += rp[j] * e;
                    }
                }
            }
        }
        block_finish(0.0f, -s_corr, 3, 4, out);

    } else {
        // ======== Alignments main pass: 4x unrolled batched loads ========
        __shared__ int s_li[B_], s_lo[B_];
        if (threadIdx.x < B_) {
            s_li[threadIdx.x] = in_len[threadIdx.x];
            s_lo[threadIdx.x] = out_len[threadIdx.x];
        }
        __syncthreads();

        int lblk = blk - G_MEL - G_GATE - G_CORR;
        float s_att = 0.0f, s_ga = 0.0f;
        const int stride = G_ALIGN * 256;
        int idx = lblk * 256 + threadIdx.x;
        for (; idx + 3 * stride < N_AL4; idx += 4 * stride) {
            float4 a0 = al[idx];
            float4 a1 = al[idx + stride];
            float4 a2 = al[idx + 2 * stride];
            float4 a3 = al[idx + 3 * stride];
            align_elem(a0, idx,              s_li, s_lo, s_att, s_ga);
            align_elem(a1, idx + stride,     s_li, s_lo, s_att, s_ga);
            align_elem(a2, idx + 2 * stride, s_li, s_lo, s_att, s_ga);
            align_elem(a3, idx + 3 * stride, s_li, s_lo, s_att, s_ga);
        }
        for (; idx < N_AL4; idx += stride) {
            float4 a = al[idx];
            align_elem(a, idx, s_li, s_lo, s_att, s_ga);
        }
        block_finish(s_att, s_ga, 3, 4, out);
    }
}

extern "C" void kernel_launch(void* const* d_in, const int* in_sizes, int n_in,
                              void* d_out, int out_size) {
    const float* mel_out         = (const float*)d_in[0];
    const float* mel_out_postnet = (const float*)d_in[1];
    const float* gate_out        = (const float*)d_in[2];
    const float* alignments      = (const float*)d_in[3];
    const float* mel_target      = (const float*)d_in[4];
    const float* gate_target     = (const float*)d_in[5];
    const int*   input_lengths   = (const int*)d_in[6];
    const int*   output_lengths  = (const int*)d_in[7];
    float* out = (float*)d_out;

    fused_kernel<<<G_TOTAL, 256>>>((const float4*)mel_out,
                                   (const float4*)mel_out_postnet,
                                   (const float4*)mel_target,
                                   (const float4*)gate_out,
                                   (const float4*)gate_target,
                                   (const float4*)alignments,
                                   alignments,
                                   input_lengths, output_lengths,
                                   out);
}

// round 5
// speedup vs baseline: 1.3798x; 1.1490x over previous
#include <cuda_runtime.h>
#include <cuda_bf16.h>
#include <math.h>

// Fixed problem shapes
#define B_   64
#define M_   80
#define TOUT 2000
#define TIN  400

#define N_MEL   (B_ * M_ * TOUT)          // 10,240,000
#define N_MEL4  (N_MEL / 4)               // 2,560,000
#define N_GATE  (B_ * TOUT)               // 128,000
#define N_GATE4 (N_GATE / 4)              // 32,000
#define N_ROWS  (B_ * TOUT)               // 128,000 alignment rows
#define N_AL4   (N_ROWS * 100)            // 12,800,000 float4
#define TIN4    (TIN / 4)                 // 100 float4 per row

#define INV2SIG2 3.125f                   // 1/(2*0.4^2)
#define BAND     2.45f                    // exp(-3.125*2.45^2) ~ 6e-9 (negligible)

// One wave: 148 SMs x occ 6 = 888 identical blocks. Every block runs every
// phase over its own stripe -> perfect load balance, no section tail.
#define G_TOTAL 888
#define NTHREAD 256
#define TSTRIDE (G_TOTAL * NTHREAD)       // 227,328 threads

// Accumulators: 0=mel1, 1=mel2, 2=gate, 3=att, 4=ga
// Zero-initialized statics; last finishing block re-zeroes after reading.
__device__ double g_acc[5];
__device__ unsigned int g_done;

__device__ __forceinline__ float warp_sum(float v) {
    #pragma unroll
    for (int o = 16; o > 0; o >>= 1)
        v += __shfl_xor_sync(0xFFFFFFFFu, v, o);
    return v;
}

__device__ __forceinline__ float bce1(float x, float z) {
    return fmaxf(x, 0.0f) - x * z + log1pf(expf(-fabsf(x)));
}

// per-float4 align contribution (att + ga masked sums)
__device__ __forceinline__ void align_elem(float4 a, int idx,
                                           const int* __restrict__ s_li,
                                           const int* __restrict__ s_lo,
                                           float& s_att, float& s_ga) {
    unsigned uidx = (unsigned)idx;
    unsigned j4  = uidx % TIN4;
    unsigned row = uidx / TIN4;
    unsigned b   = row / TOUT;
    int      i   = (int)(row - b * TOUT);
    int      j0  = (int)(j4 << 2);

    float sfull = (a.x + a.y) + (a.z + a.w);

    // att: sum over j < i
    if (j0 + 4 <= i) {
        s_att += sfull;
    } else if (j0 < i) {
        s_att += ((j0     < i ? a.x : 0.0f) + (j0 + 1 < i ? a.y : 0.0f))
               + ((j0 + 2 < i ? a.z : 0.0f) + (j0 + 3 < i ? a.w : 0.0f));
    }

    // ga main: valid region (i<lo, j<li); w==1 outside the narrow exp band
    int limG = (i < s_lo[b]) ? s_li[b] : 0;
    if (j0 + 4 <= limG) {
        s_ga += sfull;
    } else if (j0 < limG) {
        s_ga += ((j0     < limG ? a.x : 0.0f) + (j0 + 1 < limG ? a.y : 0.0f))
              + ((j0 + 2 < limG ? a.z : 0.0f) + (j0 + 3 < limG ? a.w : 0.0f));
    }
}

__global__ void __launch_bounds__(NTHREAD, 6)
fused_kernel(const float4* __restrict__ mo,
             const float4* __restrict__ mp,
             const float4* __restrict__ mt,
             const float4* __restrict__ go,
             const float4* __restrict__ gt,
             const float4* __restrict__ al,
             const float*  __restrict__ al_s,
             const int*    __restrict__ in_len,
             const int*    __restrict__ out_len,
             float*        __restrict__ out) {
    __shared__ int s_li[B_], s_lo[B_];
    if (threadIdx.x < B_) {
        s_li[threadIdx.x] = in_len[threadIdx.x];
        s_lo[threadIdx.x] = out_len[threadIdx.x];
    }
    __syncthreads();

    const int gtid = blockIdx.x * NTHREAD + threadIdx.x;

    // ======== Phase 1: Gate BCE (tiny: <1 float4 per thread) ========
    float s_gate = 0.0f;
    for (int i = gtid; i < N_GATE4; i += TSTRIDE) {
        float4 x = go[i];
        float4 z = gt[i];
        s_gate += bce1(x.x, z.x) + bce1(x.y, z.y) + bce1(x.z, z.z) + bce1(x.w, z.w);
    }

    // ======== Phase 2: guided-attention band correction ========
    // -sum a*exp(-d^2/(2 sigma^2)); only |i - j*lo/li| <= BAND contributes
    // (scale = lo/li >= 2.5 -> at most ~2 j per row, k in 0..3 covers it)
    float s_corr = 0.0f;
    for (int row = gtid; row < N_ROWS; row += TSTRIDE) {
        int b = row / TOUT;
        int i = row - b * TOUT;
        int li = s_li[b];
        int lo = s_lo[b];
        if (i < lo) {
            float fli = (float)li, flo = (float)lo, fi = (float)i;
            float inv_scale = __fdividef(fli, flo);   // li/lo
            float scale     = __fdividef(flo, fli);   // lo/li
            int j0c = (int)floorf((fi - BAND) * inv_scale);
            const float* rp = al_s + (long)row * TIN;
            #pragma unroll
            for (int k = 0; k < 4; k++) {
                int j = j0c + k;
                if (j >= 0 && j < li) {
                    float d = fmaf((float)j, -scale, fi);
                    float e = __expf(-d * d * INV2SIG2);
                    s_corr += rp[j] * e;
                }
            }
        }
    }

    // ======== Phase 3: Mel L1 (decoder + postnet), 2x unrolled ========
    float s1 = 0.0f, s2 = 0.0f;
    {
        int i = gtid;
        for (; i + TSTRIDE < N_MEL4; i += 2 * TSTRIDE) {
            float4 a0 = mo[i], a1 = mo[i + TSTRIDE];
            float4 p0 = mp[i], p1 = mp[i + TSTRIDE];
            float4 t0 = mt[i], t1 = mt[i + TSTRIDE];
            s1 += fabsf(a0.x - t0.x) + fabsf(a0.y - t0.y) + fabsf(a0.z - t0.z) + fabsf(a0.w - t0.w);
            s2 += fabsf(p0.x - t0.x) + fabsf(p0.y - t0.y) + fabsf(p0.z - t0.z) + fabsf(p0.w - t0.w);
            s1 += fabsf(a1.x - t1.x) + fabsf(a1.y - t1.y) + fabsf(a1.z - t1.z) + fabsf(a1.w - t1.w);
            s2 += fabsf(p1.x - t1.x) + fabsf(p1.y - t1.y) + fabsf(p1.z - t1.z) + fabsf(p1.w - t1.w);
        }
        for (; i < N_MEL4; i += TSTRIDE) {
            float4 a = mo[i], p = mp[i], t = mt[i];
            s1 += fabsf(a.x - t.x) + fabsf(a.y - t.y) + fabsf(a.z - t.z) + fabsf(a.w - t.w);
            s2 += fabsf(p.x - t.x) + fabsf(p.y - t.y) + fabsf(p.z - t.z) + fabsf(p.w - t.w);
        }
    }

    // ======== Phase 4: Alignments main pass, 4x unrolled batched loads ========
    float s_att = 0.0f, s_ga = 0.0f;
    {
        int idx = gtid;
        for (; idx + 3 * TSTRIDE < N_AL4; idx += 4 * TSTRIDE) {
            float4 a0 = al[idx];
            float4 a1 = al[idx + TSTRIDE];
            float4 a2 = al[idx + 2 * TSTRIDE];
            float4 a3 = al[idx + 3 * TSTRIDE];
            align_elem(a0, idx,               s_li, s_lo, s_att, s_ga);
            align_elem(a1, idx + TSTRIDE,     s_li, s_lo, s_att, s_ga);
            align_elem(a2, idx + 2 * TSTRIDE, s_li, s_lo, s_att, s_ga);
            align_elem(a3, idx + 3 * TSTRIDE, s_li, s_lo, s_att, s_ga);
        }
        for (; idx < N_AL4; idx += TSTRIDE) {
            float4 a = al[idx];
            align_elem(a, idx, s_li, s_lo, s_att, s_ga);
        }
    }
    s_ga -= s_corr;

    // ======== Block reduce all 5 sums, atomics, last-block finalize ========
    __shared__ float sh[5][8];
    int lane = threadIdx.x & 31;
    int wid  = threadIdx.x >> 5;
    float v0 = warp_sum(s1);
    float v1 = warp_sum(s2);
    float v2 = warp_sum(s_gate);
    float v3 = warp_sum(s_att);
    float v4 = warp_sum(s_ga);
    if (lane == 0) {
        sh[0][wid] = v0; sh[1][wid] = v1; sh[2][wid] = v2;
        sh[3][wid] = v3; sh[4][wid] = v4;
    }
    __syncthreads();
    if (wid == 0) {
        v0 = warp_sum((lane < 8) ? sh[0][lane] : 0.0f);
        v1 = warp_sum((lane < 8) ? sh[1][lane] : 0.0f);
        v2 = warp_sum((lane < 8) ? sh[2][lane] : 0.0f);
        v3 = warp_sum((lane < 8) ? sh[3][lane] : 0.0f);
        v4 = warp_sum((lane < 8) ? sh[4][lane] : 0.0f);
        if (lane == 0) {
            atomicAdd(&g_acc[0], (double)v0);
            atomicAdd(&g_acc[1], (double)v1);
            atomicAdd(&g_acc[2], (double)v2);
            atomicAdd(&g_acc[3], (double)v3);
            atomicAdd(&g_acc[4], (double)v4);
            __threadfence();
            unsigned int t = atomicAdd(&g_done, 1u);
            if (t == (unsigned)(G_TOTAL - 1)) {
                volatile double* acc = g_acc;
                double mel  = (acc[0] + acc[1]) / (double)N_MEL;
                double gate = acc[2] / (double)N_GATE;
                double att  = acc[3] / (double)B_;
                double ga   = acc[4] / (double)B_;
                double total = mel + gate + 0.1 * att + 0.1 * ga;
                out[0] = (float)total;
                out[1] = (float)mel;
                out[2] = (float)gate;
                out[3] = (float)att;
                out[4] = (float)ga;
                acc[0] = 0.0; acc[1] = 0.0; acc[2] = 0.0; acc[3] = 0.0; acc[4] = 0.0;
                g_done = 0u;
                __threadfence();
            }
        }
    }
}

extern "C" void kernel_launch(void* const* d_in, const int* in_sizes, int n_in,
                              void* d_out, int out_size) {
    const float* mel_out         = (const float*)d_in[0];
    const float* mel_out_postnet = (const float*)d_in[1];
    const float* gate_out        = (const float*)d_in[2];
    const float* alignments      = (const float*)d_in[3];
    const float* mel_target      = (const float*)d_in[4];
    const float* gate_target     = (const float*)d_in[5];
    const int*   input_lengths   = (const int*)d_in[6];
    const int*   output_lengths  = (const int*)d_in[7];
    float* out = (float*)d_out;

    fused_kernel<<<G_TOTAL, NTHREAD>>>((const float4*)mel_out,
                                       (const float4*)mel_out_postnet,
                                       (const float4*)mel_target,
                                       (const float4*)gate_out,
                                       (const float4*)gate_target,
                                       (const float4*)alignments,
                                       alignments,
                                       input_lengths, output_lengths,
                                       out);
}

// round 7
// speedup vs baseline: 1.3850x; 1.0038x over previous
#include <cuda_runtime.h>
#include <cuda_bf16.h>
#include <math.h>

// Fixed problem shapes
#define B_   64
#define M_   80
#define TOUT 2000
#define TIN  400

#define N_MEL   (B_ * M_ * TOUT)          // 10,240,000
#define N_MEL4  (N_MEL / 4)               // 2,560,000
#define N_GATE  (B_ * TOUT)               // 128,000
#define N_GATE4 (N_GATE / 4)              // 32,000
#define N_ROWS  (B_ * TOUT)               // 128,000 alignment rows
#define N_AL4   (N_ROWS * 100)            // 12,800,000 float4
#define TIN4    (TIN / 4)                 // 100 float4 per row
#define NGRP    (N_AL4 / 4)               // 3,200,000 64B groups (25 per row, exact)

#define INV2SIG2 3.125f                   // 1/(2*0.4^2)
#define BAND     2.45f                    // exp(-3.125*2.45^2) ~ 6e-9 (negligible)

// One wave: 148 SMs x occ 6 = 888 identical blocks; every block runs every
// phase over its own stripe (perfect balance, no section tail).
#define G_TOTAL 888
#define NTHREAD 256
#define TSTRIDE (G_TOTAL * NTHREAD)       // 227,328 threads

// Accumulators: 0=mel1, 1=mel2, 2=gate, 3=att, 4=ga
// Zero-initialized statics; last finishing block re-zeroes after reading.
__device__ double g_acc[5];
__device__ unsigned int g_done;

__device__ __forceinline__ float warp_sum(float v) {
    #pragma unroll
    for (int o = 16; o > 0; o >>= 1)
        v += __shfl_xor_sync(0xFFFFFFFFu, v, o);
    return v;
}

__device__ __forceinline__ float bce1(float x, float z) {
    return fmaxf(x, 0.0f) - x * z + log1pf(expf(-fabsf(x)));
}

// masked sum of one float4 sub-block against limit `lim` (elements j0..j0+3)
__device__ __forceinline__ float sub_masked(float4 a, float sf, int j0, int lim) {
    if (j0 + 4 <= lim) return sf;
    return ((j0     < lim ? a.x : 0.0f) + (j0 + 1 < lim ? a.y : 0.0f))
         + ((j0 + 2 < lim ? a.z : 0.0f) + (j0 + 3 < lim ? a.w : 0.0f));
}

__global__ void __launch_bounds__(NTHREAD, 6)
fused_kernel(const float4* __restrict__ mo,
             const float4* __restrict__ mp,
             const float4* __restrict__ mt,
             const float4* __restrict__ go,
             const float4* __restrict__ gt,
             const float4* __restrict__ al,
             const float*  __restrict__ al_s,
             const int*    __restrict__ in_len,
             const int*    __restrict__ out_len,
             float*        __restrict__ out) {
    __shared__ int s_li[B_], s_lo[B_];
    if (threadIdx.x < B_) {
        s_li[threadIdx.x] = in_len[threadIdx.x];
        s_lo[threadIdx.x] = out_len[threadIdx.x];
    }
    __syncthreads();

    const int gtid = blockIdx.x * NTHREAD + threadIdx.x;

    // ======== Phase 1: Gate BCE (tiny) ========
    float s_gate = 0.0f;
    for (int i = gtid; i < N_GATE4; i += TSTRIDE) {
        float4 x = go[i];
        float4 z = gt[i];
        s_gate += bce1(x.x, z.x) + bce1(x.y, z.y) + bce1(x.z, z.z) + bce1(x.w, z.w);
    }

    // ======== Phase 2: guided-attention band correction ========
    // -sum a*exp(-d^2/(2 sigma^2)); only |i - j*lo/li| <= BAND contributes
    float s_corr = 0.0f;
    for (int row = gtid; row < N_ROWS; row += TSTRIDE) {
        int b = row / TOUT;
        int i = row - b * TOUT;
        int li = s_li[b];
        int lo = s_lo[b];
        if (i < lo) {
            float fli = (float)li, flo = (float)lo, fi = (float)i;
            float inv_scale = __fdividef(fli, flo);   // li/lo
            float scale     = __fdividef(flo, fli);   // lo/li
            int j0c = (int)floorf((fi - BAND) * inv_scale);
            const float* rp = al_s + (long)row * TIN;
            #pragma unroll
            for (int k = 0; k < 4; k++) {
                int j = j0c + k;
                if (j >= 0 && j < li) {
                    float d = fmaf((float)j, -scale, fi);
                    float e = __expf(-d * d * INV2SIG2);
                    s_corr += rp[j] * e;
                }
            }
        }
    }

    // ======== Phase 3: Mel L1 (decoder + postnet), 2x unrolled ========
    float s1 = 0.0f, s2 = 0.0f;
    {
        int i = gtid;
        for (; i + TSTRIDE < N_MEL4; i += 2 * TSTRIDE) {
            float4 a0 = mo[i], a1 = mo[i + TSTRIDE];
            float4 p0 = mp[i], p1 = mp[i + TSTRIDE];
            float4 t0 = mt[i], t1 = mt[i + TSTRIDE];
            s1 += fabsf(a0.x - t0.x) + fabsf(a0.y - t0.y) + fabsf(a0.z - t0.z) + fabsf(a0.w - t0.w);
            s2 += fabsf(p0.x - t0.x) + fabsf(p0.y - t0.y) + fabsf(p0.z - t0.z) + fabsf(p0.w - t0.w);
            s1 += fabsf(a1.x - t1.x) + fabsf(a1.y - t1.y) + fabsf(a1.z - t1.z) + fabsf(a1.w - t1.w);
            s2 += fabsf(p1.x - t1.x) + fabsf(p1.y - t1.y) + fabsf(p1.z - t1.z) + fabsf(p1.w - t1.w);
        }
        for (; i < N_MEL4; i += TSTRIDE) {
            float4 a = mo[i], p = mp[i], t = mt[i];
            s1 += fabsf(a.x - t.x) + fabsf(a.y - t.y) + fabsf(a.z - t.z) + fabsf(a.w - t.w);
            s2 += fabsf(p.x - t.x) + fabsf(p.y - t.y) + fabsf(p.z - t.z) + fabsf(p.w - t.w);
        }
    }

    // ======== Phase 4: Alignments, 64B groups (4 consecutive float4 / thread) ========
    // One index decode + one limit pair serves 16 elements. Exactly 25 groups
    // per row, so a group never straddles rows.
    float s_att = 0.0f, s_ga = 0.0f;
    for (int g = gtid; g < NGRP; g += TSTRIDE) {
        unsigned ug  = (unsigned)g;
        unsigned row = ug / 25u;
        unsigned jg  = ug - row * 25u;
        unsigned b   = row / TOUT;
        int      i   = (int)(row - b * TOUT);
        int      j0  = (int)(jg << 4);        // first element index of the 16

        const float4* p = al + ((long)row * TIN4 + (jg << 2));
        float4 a0 = p[0];
        float4 a1 = p[1];
        float4 a2 = p[2];
        float4 a3 = p[3];

        float sf0 = (a0.x + a0.y) + (a0.z + a0.w);
        float sf1 = (a1.x + a1.y) + (a1.z + a1.w);
        float sf2 = (a2.x + a2.y) + (a2.z + a2.w);
        float sf3 = (a3.x + a3.y) + (a3.z + a3.w);
        float sum_all = (sf0 + sf1) + (sf2 + sf3);

        int limG = (i < s_lo[b]) ? s_li[b] : 0;

        // att: sum over j < i
        if (j0 + 16 <= i) {
            s_att += sum_all;
        } else if (j0 < i) {
            s_att += (sub_masked(a0, sf0, j0,      i) + sub_masked(a1, sf1, j0 + 4,  i))
                   + (sub_masked(a2, sf2, j0 + 8,  i) + sub_masked(a3, sf3, j0 + 12, i));
        }

        // ga main: valid region sum (w==1 outside the narrow exp band)
        if (j0 + 16 <= limG) {
            s_ga += sum_all;
        } else if (j0 < limG) {
            s_ga += (sub_masked(a0, sf0, j0,      limG) + sub_masked(a1, sf1, j0 + 4,  limG))
                  + (sub_masked(a2, sf2, j0 + 8,  limG) + sub_masked(a3, sf3, j0 + 12, limG));
        }
    }
    s_ga -= s_corr;

    // ======== Block reduce all 5 sums, atomics, last-block finalize ========
    __shared__ float sh[5][8];
    int lane = threadIdx.x & 31;
    int wid  = threadIdx.x >> 5;
    float v0 = warp_sum(s1);
    float v1 = warp_sum(s2);
    float v2 = warp_sum(s_gate);
    float v3 = warp_sum(s_att);
    float v4 = warp_sum(s_ga);
    if (lane == 0) {
        sh[0][wid] = v0; sh[1][wid] = v1; sh[2][wid] = v2;
        sh[3][wid] = v3; sh[4][wid] = v4;
    }
    __syncthreads();
    if (wid == 0) {
        v0 = warp_sum((lane < 8) ? sh[0][lane] : 0.0f);
        v1 = warp_sum((lane < 8) ? sh[1][lane] : 0.0f);
        v2 = warp_sum((lane < 8) ? sh[2][lane] : 0.0f);
        v3 = warp_sum((lane < 8) ? sh[3][lane] : 0.0f);
        v4 = warp_sum((lane < 8) ? sh[4][lane] : 0.0f);
        if (lane == 0) {
            atomicAdd(&g_acc[0], (double)v0);
            atomicAdd(&g_acc[1], (double)v1);
            atomicAdd(&g_acc[2], (double)v2);
            atomicAdd(&g_acc[3], (double)v3);
            atomicAdd(&g_acc[4], (double)v4);
            __threadfence();
            unsigned int t = atomicAdd(&g_done, 1u);
            if (t == (unsigned)(G_TOTAL - 1)) {
                volatile double* acc = g_acc;
                double mel  = (acc[0] + acc[1]) / (double)N_MEL;
                double gate = acc[2] / (double)N_GATE;
                double att  = acc[3] / (double)B_;
                double ga   = acc[4] / (double)B_;
                double total = mel + gate + 0.1 * att + 0.1 * ga;
                out[0] = (float)total;
                out[1] = (float)mel;
                out[2] = (float)gate;
                out[3] = (float)att;
                out[4] = (float)ga;
                acc[0] = 0.0; acc[1] = 0.0; acc[2] = 0.0; acc[3] = 0.0; acc[4] = 0.0;
                g_done = 0u;
                __threadfence();
            }
        }
    }
}

extern "C" void kernel_launch(void* const* d_in, const int* in_sizes, int n_in,
                              void* d_out, int out_size) {
    const float* mel_out         = (const float*)d_in[0];
    const float* mel_out_postnet = (const float*)d_in[1];
    const float* gate_out        = (const float*)d_in[2];
    const float* alignments      = (const float*)d_in[3];
    const float* mel_target      = (const float*)d_in[4];
    const float* gate_target     = (const float*)d_in[5];
    const int*   input_lengths   = (const int*)d_in[6];
    const int*   output_lengths  = (const int*)d_in[7];
    float* out = (float*)d_out;

    fused_kernel<<<G_TOTAL, NTHREAD>>>((const float4*)mel_out,
                                       (const float4*)mel_out_postnet,
                                       (const float4*)mel_target,
                                       (const float4*)gate_out,
                                       (const float4*)gate_target,
                                       (const float4*)alignments,
                                       alignments,
                                       input_lengths, output_lengths,
                                       out);
}

// round 9
// speedup vs baseline: 1.4640x; 1.0571x over previous
#include <cuda_runtime.h>
#include <cuda_bf16.h>
#include <math.h>

// Fixed problem shapes
#define B_   64
#define M_   80
#define TOUT 2000
#define TIN  400

#define N_MEL   (B_ * M_ * TOUT)          // 10,240,000
#define N_MEL4  (N_MEL / 4)               // 2,560,000
#define N_GATE  (B_ * TOUT)               // 128,000
#define N_GATE4 (N_GATE / 4)              // 32,000
#define N_ROWS  (B_ * TOUT)               // 128,000 alignment rows
#define N_AL4   (N_ROWS * 100)            // 12,800,000 float4
#define TIN4    (TIN / 4)                 // 100 float4 per row

#define INV2SIG2 3.125f                   // 1/(2*0.4^2)
#define BAND     2.45f                    // exp(-3.125*2.45^2) ~ 6e-9 (negligible)

// One wave: 148 SMs x occ 6 = 888 identical blocks; every block runs every
// phase over its own stripe (perfect balance, no section tail).
#define G_TOTAL 888
#define NTHREAD 256
#define TSTRIDE (G_TOTAL * NTHREAD)       // 227,328 threads

// Accumulators: 0=mel1, 1=mel2, 2=gate, 3=att, 4=ga
// Zero-initialized statics; last finishing block re-zeroes after reading.
__device__ double g_acc[5];
__device__ unsigned int g_done;

__device__ __forceinline__ float warp_sum(float v) {
    #pragma unroll
    for (int o = 16; o > 0; o >>= 1)
        v += __shfl_xor_sync(0xFFFFFFFFu, v, o);
    return v;
}

__device__ __forceinline__ float bce1(float x, float z) {
    return fmaxf(x, 0.0f) - x * z + log1pf(expf(-fabsf(x)));
}

// per-float4 align contribution (att + ga masked sums)
__device__ __forceinline__ void align_elem(float4 a, int idx,
                                           const int* __restrict__ s_li,
                                           const int* __restrict__ s_lo,
                                           float& s_att, float& s_ga) {
    unsigned uidx = (unsigned)idx;
    unsigned j4  = uidx % TIN4;
    unsigned row = uidx / TIN4;
    unsigned b   = row / TOUT;
    int      i   = (int)(row - b * TOUT);
    int      j0  = (int)(j4 << 2);

    float sfull = (a.x + a.y) + (a.z + a.w);

    // att: sum over j < i
    if (j0 + 4 <= i) {
        s_att += sfull;
    } else if (j0 < i) {
        s_att += ((j0     < i ? a.x : 0.0f) + (j0 + 1 < i ? a.y : 0.0f))
               + ((j0 + 2 < i ? a.z : 0.0f) + (j0 + 3 < i ? a.w : 0.0f));
    }

    // ga main: valid region (i<lo, j<li); w==1 outside the narrow exp band
    int limG = (i < s_lo[b]) ? s_li[b] : 0;
    if (j0 + 4 <= limG) {
        s_ga += sfull;
    } else if (j0 < limG) {
        s_ga += ((j0     < limG ? a.x : 0.0f) + (j0 + 1 < limG ? a.y : 0.0f))
              + ((j0 + 2 < limG ? a.z : 0.0f) + (j0 + 3 < limG ? a.w : 0.0f));
    }
}

__global__ void __launch_bounds__(NTHREAD, 6)
fused_kernel(const float4* __restrict__ mo,
             const float4* __restrict__ mp,
             const float4* __restrict__ mt,
             const float4* __restrict__ go,
             const float4* __restrict__ gt,
             const float4* __restrict__ al,
             const float*  __restrict__ al_s,
             const int*    __restrict__ in_len,
             const int*    __restrict__ out_len,
             float*        __restrict__ out) {
    __shared__ int s_li[B_], s_lo[B_];
    if (threadIdx.x < B_) {
        s_li[threadIdx.x] = in_len[threadIdx.x];
        s_lo[threadIdx.x] = out_len[threadIdx.x];
    }
    __syncthreads();

    const int gtid = blockIdx.x * NTHREAD + threadIdx.x;

    // ======== Phase 1: Gate BCE (tiny) ========
    float s_gate = 0.0f;
    for (int i = gtid; i < N_GATE4; i += TSTRIDE) {
        float4 x = __ldcs(&go[i]);
        float4 z = __ldcs(&gt[i]);
        s_gate += bce1(x.x, z.x) + bce1(x.y, z.y) + bce1(x.z, z.z) + bce1(x.w, z.w);
    }

    // ======== Phase 2: guided-attention band correction ========
    // -sum a*exp(-d^2/(2 sigma^2)); only |i - j*lo/li| <= BAND contributes.
    // Default caching: these lines are re-read by phase 4 and can sit in L2.
    float s_corr = 0.0f;
    for (int row = gtid; row < N_ROWS; row += TSTRIDE) {
        int b = row / TOUT;
        int i = row - b * TOUT;
        int li = s_li[b];
        int lo = s_lo[b];
        if (i < lo) {
            float fli = (float)li, flo = (float)lo, fi = (float)i;
            float inv_scale = __fdividef(fli, flo);   // li/lo
            float scale     = __fdividef(flo, fli);   // lo/li
            int j0c = (int)floorf((fi - BAND) * inv_scale);
            const float* rp = al_s + (long)row * TIN;
            #pragma unroll
            for (int k = 0; k < 4; k++) {
                int j = j0c + k;
                if (j >= 0 && j < li) {
                    float d = fmaf((float)j, -scale, fi);
                    float e = __expf(-d * d * INV2SIG2);
                    s_corr += __ldg(&rp[j]) * e;
                }
            }
        }
    }

    // ======== Phase 3: Mel L1 (decoder + postnet), 2x unrolled, streaming ========
    float s1 = 0.0f, s2 = 0.0f;
    {
        int i = gtid;
        for (; i + TSTRIDE < N_MEL4; i += 2 * TSTRIDE) {
            float4 a0 = __ldcs(&mo[i]), a1 = __ldcs(&mo[i + TSTRIDE]);
            float4 p0 = __ldcs(&mp[i]), p1 = __ldcs(&mp[i + TSTRIDE]);
            float4 t0 = __ldcs(&mt[i]), t1 = __ldcs(&mt[i + TSTRIDE]);
            s1 += fabsf(a0.x - t0.x) + fabsf(a0.y - t0.y) + fabsf(a0.z - t0.z) + fabsf(a0.w - t0.w);
            s2 += fabsf(p0.x - t0.x) + fabsf(p0.y - t0.y) + fabsf(p0.z - t0.z) + fabsf(p0.w - t0.w);
            s1 += fabsf(a1.x - t1.x) + fabsf(a1.y - t1.y) + fabsf(a1.z - t1.z) + fabsf(a1.w - t1.w);
            s2 += fabsf(p1.x - t1.x) + fabsf(p1.y - t1.y) + fabsf(p1.z - t1.z) + fabsf(p1.w - t1.w);
        }
        for (; i < N_MEL4; i += TSTRIDE) {
            float4 a = __ldcs(&mo[i]), p = __ldcs(&mp[i]), t = __ldcs(&mt[i]);
            s1 += fabsf(a.x - t.x) + fabsf(a.y - t.y) + fabsf(a.z - t.z) + fabsf(a.w - t.w);
            s2 += fabsf(p.x - t.x) + fabsf(p.y - t.y) + fabsf(p.z - t.z) + fabsf(p.w - t.w);
        }
    }

    // ======== Phase 4: Alignments main pass, warp-contiguous float4, 4x batched ========
    float s_att = 0.0f, s_ga = 0.0f;
    {
        int idx = gtid;
        for (; idx + 3 * TSTRIDE < N_AL4; idx += 4 * TSTRIDE) {
            float4 a0 = __ldcs(&al[idx]);
            float4 a1 = __ldcs(&al[idx + TSTRIDE]);
            float4 a2 = __ldcs(&al[idx + 2 * TSTRIDE]);
            float4 a3 = __ldcs(&al[idx + 3 * TSTRIDE]);
            align_elem(a0, idx,               s_li, s_lo, s_att, s_ga);
            align_elem(a1, idx + TSTRIDE,     s_li, s_lo, s_att, s_ga);
            align_elem(a2, idx + 2 * TSTRIDE, s_li, s_lo, s_att, s_ga);
            align_elem(a3, idx + 3 * TSTRIDE, s_li, s_lo, s_att, s_ga);
        }
        for (; idx < N_AL4; idx += TSTRIDE) {
            float4 a = __ldcs(&al[idx]);
            align_elem(a, idx, s_li, s_lo, s_att, s_ga);
        }
    }
    s_ga -= s_corr;

    // ======== Block reduce all 5 sums, atomics, last-block finalize ========
    __shared__ float sh[5][8];
    int lane = threadIdx.x & 31;
    int wid  = threadIdx.x >> 5;
    float v0 = warp_sum(s1);
    float v1 = warp_sum(s2);
    float v2 = warp_sum(s_gate);
    float v3 = warp_sum(s_att);
    float v4 = warp_sum(s_ga);
    if (lane == 0) {
        sh[0][wid] = v0; sh[1][wid] = v1; sh[2][wid] = v2;
        sh[3][wid] = v3; sh[4][wid] = v4;
    }
    __syncthreads();
    if (wid == 0) {
        v0 = warp_sum((lane < 8) ? sh[0][lane] : 0.0f);
        v1 = warp_sum((lane < 8) ? sh[1][lane] : 0.0f);
        v2 = warp_sum((lane < 8) ? sh[2][lane] : 0.0f);
        v3 = warp_sum((lane < 8) ? sh[3][lane] : 0.0f);
        v4 = warp_sum((lane < 8) ? sh[4][lane] : 0.0f);
        if (lane == 0) {
            atomicAdd(&g_acc[0], (double)v0);
            atomicAdd(&g_acc[1], (double)v1);
            atomicAdd(&g_acc[2], (double)v2);
            atomicAdd(&g_acc[3], (double)v3);
            atomicAdd(&g_acc[4], (double)v4);
            __threadfence();
            unsigned int t = atomicAdd(&g_done, 1u);
            if (t == (unsigned)(G_TOTAL - 1)) {
                volatile double* acc = g_acc;
                double mel  = (acc[0] + acc[1]) / (double)N_MEL;
                double gate = acc[2] / (double)N_GATE;
                double att  = acc[3] / (double)B_;
                double ga   = acc[4] / (double)B_;
                double total = mel + gate + 0.1 * att + 0.1 * ga;
                out[0] = (float)total;
                out[1] = (float)mel;
                out[2] = (float)gate;
                out[3] = (float)att;
                out[4] = (float)ga;
                acc[0] = 0.0; acc[1] = 0.0; acc[2] = 0.0; acc[3] = 0.0; acc[4] = 0.0;
                g_done = 0u;
                __threadfence();
            }
        }
    }
}

extern "C" void kernel_launch(void* const* d_in, const int* in_sizes, int n_in,
                              void* d_out, int out_size) {
    const float* mel_out         = (const float*)d_in[0];
    const float* mel_out_postnet = (const float*)d_in[1];
    const float* gate_out        = (const float*)d_in[2];
    const float* alignments      = (const float*)d_in[3];
    const float* mel_target      = (const float*)d_in[4];
    const float* gate_target     = (const float*)d_in[5];
    const int*   input_lengths   = (const int*)d_in[6];
    const int*   output_lengths  = (const int*)d_in[7];
    float* out = (float*)d_out;

    fused_kernel<<<G_TOTAL, NTHREAD>>>((const float4*)mel_out,
                                       (const float4*)mel_out_postnet,
                                       (const float4*)mel_target,
                                       (const float4*)gate_out,
                                       (const float4*)gate_target,
                                       (const float4*)alignments,
                                       alignments,
                                       input_lengths, output_lengths,
                                       out);
}